// round 4
// baseline (speedup 1.0000x reference)
#include <cuda_runtime.h>

#define H 4
#define MAXN 100000
#define MAXE 1000000
#define NEG 0.2f
#define EPSF 1e-16f

// ---------------- scratch (device globals; no allocation allowed) ----------------
__device__ __align__(16) float g_h1[MAXN * 128];     // layer1 features [N, H*32]
__device__ __align__(16) float g_accum1[MAXN * 128]; // weighted sums
__device__ __align__(16) float g_as1[MAXN * H];
__device__ __align__(16) float g_ad1[MAXN * H];
__device__ __align__(16) float g_denom1[MAXN * H];
__device__ __align__(16) float g_x2[MAXN * 32];      // relu(layer1 out)
__device__ __align__(16) float g_h2[MAXN * 64];      // layer2 features [N, H*16]
__device__ __align__(16) float g_accum2[MAXN * 64];
__device__ __align__(16) float g_as2[MAXN * H];
__device__ __align__(16) float g_ad2[MAXN * H];
__device__ __align__(16) float g_denom2[MAXN * H];
__device__ int g_src[MAXE];
__device__ int g_dst[MAXE];
__device__ int g_is64;

// ---------------- dtype sniffer: int64 edge_index has zero high words ----------------
__global__ void detect_kernel(const int* __restrict__ ei_raw) {
    if (threadIdx.x == 0 && blockIdx.x == 0) {
        int all0 = 1;
        for (int i = 0; i < 32; i++)
            if (ei_raw[2 * i + 1] != 0) { all0 = 0; break; }
        g_is64 = all0;
    }
}

// ---------------- decode edge list to int32 (clamped; crash-proof) ----------------
__global__ void decode_kernel(const void* __restrict__ ei, int E, int N) {
    int e = blockIdx.x * blockDim.x + threadIdx.x;
    if (e >= E) return;
    int is64 = g_is64;
    int s, d;
    if (is64) {
        s = (int)((const long long*)ei)[e];
        d = (int)((const long long*)ei)[E + e];
    } else {
        s = ((const int*)ei)[e];
        d = ((const int*)ei)[E + e];
    }
    s = s < 0 ? 0 : (s >= N ? N - 1 : s);
    d = d < 0 ? 0 : (d >= N ? N - 1 : d);
    g_src[e] = s;
    g_dst[e] = d;
}

// ---------------- zero scratch ----------------
__global__ void zero_kernel(int N) {
    int i = blockIdx.x * blockDim.x + threadIdx.x;
    int stride = gridDim.x * blockDim.x;
    float4 z = make_float4(0.f, 0.f, 0.f, 0.f);
    float4* a1 = (float4*)g_accum1;
    int n1 = N * 32;  // N*128 floats / 4
    for (int j = i; j < n1; j += stride) a1[j] = z;
    float4* a2 = (float4*)g_accum2;
    int n2 = N * 16;  // N*64 floats / 4
    for (int j = i; j < n2; j += stride) a2[j] = z;
    float4* d1 = (float4*)g_denom1;
    float4* d2 = (float4*)g_denom2;
    for (int j = i; j < N; j += stride) { d1[j] = z; d2[j] = z; }
}

// ---------------- GEMM1: h1[N,128] = x[N,128] @ W1[128,128] ----------------
__global__ __launch_bounds__(256) void gemm1_kernel(const float* __restrict__ x,
                                                    const float* __restrict__ W, int N) {
    __shared__ __align__(16) float xs[32][33];
    __shared__ __align__(16) float ws[32][128];
    int tid = threadIdx.x;
    int cg = tid & 31;       // column group -> cols 4*cg .. 4*cg+3
    int rowslot = tid >> 5;  // 0..7
    int rowbase = blockIdx.x * 32;
    float4 acc[4];
#pragma unroll
    for (int j = 0; j < 4; j++) acc[j] = make_float4(0.f, 0.f, 0.f, 0.f);
    for (int k0 = 0; k0 < 128; k0 += 32) {
        {
            int r = tid >> 3, kq = tid & 7;
            int row = rowbase + r;
            float4 v = make_float4(0.f, 0.f, 0.f, 0.f);
            if (row < N) v = *(const float4*)&x[row * 128 + k0 + kq * 4];
            xs[r][kq * 4 + 0] = v.x; xs[r][kq * 4 + 1] = v.y;
            xs[r][kq * 4 + 2] = v.z; xs[r][kq * 4 + 3] = v.w;
        }
#pragma unroll
        for (int i = 0; i < 4; i++) {
            int idx = tid + i * 256;
            int k = idx >> 5, c = idx & 31;
            *(float4*)&ws[k][c * 4] = *(const float4*)&W[(k0 + k) * 128 + c * 4];
        }
        __syncthreads();
#pragma unroll
        for (int k = 0; k < 32; k++) {
            float4 w = *(const float4*)&ws[k][cg * 4];
#pragma unroll
            for (int j = 0; j < 4; j++) {
                float xv = xs[rowslot + 8 * j][k];
                acc[j].x += xv * w.x; acc[j].y += xv * w.y;
                acc[j].z += xv * w.z; acc[j].w += xv * w.w;
            }
        }
        __syncthreads();
    }
#pragma unroll
    for (int j = 0; j < 4; j++) {
        int row = rowbase + rowslot + 8 * j;
        if (row < N) *(float4*)&g_h1[row * 128 + cg * 4] = acc[j];
    }
}

// ---------------- GEMM2: h2[N,64] = x2[N,32] @ W2[32,64] ----------------
__global__ __launch_bounds__(256) void gemm2_kernel(const float* __restrict__ W, int N) {
    __shared__ __align__(16) float xs[64][33];
    __shared__ __align__(16) float ws[32][64];
    int tid = threadIdx.x;
    int cg = tid & 15;       // cols 4*cg .. 4*cg+3 (of 64)
    int rowslot = tid >> 4;  // 0..15
    int rowbase = blockIdx.x * 64;
#pragma unroll
    for (int i = 0; i < 2; i++) {
        int idx = tid + i * 256;  // 0..511
        int k = idx >> 4, c = idx & 15;
        *(float4*)&ws[k][c * 4] = *(const float4*)&W[k * 64 + c * 4];
    }
#pragma unroll
    for (int i = 0; i < 2; i++) {
        int idx = tid + i * 256;  // 0..511
        int r = idx >> 3, kq = idx & 7;
        int row = rowbase + r;
        float4 v = make_float4(0.f, 0.f, 0.f, 0.f);
        if (row < N) v = *(const float4*)&g_x2[row * 32 + kq * 4];
        xs[r][kq * 4 + 0] = v.x; xs[r][kq * 4 + 1] = v.y;
        xs[r][kq * 4 + 2] = v.z; xs[r][kq * 4 + 3] = v.w;
    }
    __syncthreads();
    float4 acc[4];
#pragma unroll
    for (int j = 0; j < 4; j++) acc[j] = make_float4(0.f, 0.f, 0.f, 0.f);
#pragma unroll
    for (int k = 0; k < 32; k++) {
        float4 w = *(const float4*)&ws[k][cg * 4];
#pragma unroll
        for (int j = 0; j < 4; j++) {
            float xv = xs[rowslot + 16 * j][k];
            acc[j].x += xv * w.x; acc[j].y += xv * w.y;
            acc[j].z += xv * w.z; acc[j].w += xv * w.w;
        }
    }
#pragma unroll
    for (int j = 0; j < 4; j++) {
        int row = rowbase + rowslot + 16 * j;
        if (row < N) *(float4*)&g_h2[row * 64 + cg * 4] = acc[j];
    }
}

// ---------------- per-node attention halves: as/ad ----------------
template <int F, int LAYER>
__global__ __launch_bounds__(256) void attn_kernel(const float* __restrict__ a_src,
                                                   const float* __restrict__ a_dst, int N) {
    int i = blockIdx.x * blockDim.x + threadIdx.x;
    if (i >= N * H) return;
    int hh = i & 3;
    const float* h = (LAYER == 1) ? g_h1 : g_h2;
    float* as_ = (LAYER == 1) ? g_as1 : g_as2;
    float* ad_ = (LAYER == 1) ? g_ad1 : g_ad2;
    const float* row = h + (size_t)i * F;  // (n*H+hh)*F == n*(H*F)+hh*F
    const float* av = a_src + hh * F;
    const float* bv = a_dst + hh * F;
    float s = 0.f, d = 0.f;
#pragma unroll
    for (int f = 0; f < F; f += 4) {
        float4 hv = *(const float4*)&row[f];
        float4 a1 = *(const float4*)&av[f];
        float4 a2 = *(const float4*)&bv[f];
        s += hv.x * a1.x + hv.y * a1.y + hv.z * a1.z + hv.w * a1.w;
        d += hv.x * a2.x + hv.y * a2.y + hv.z * a2.z + hv.w * a2.w;
    }
    as_[i] = s;
    ad_[i] = d;
}

__device__ __forceinline__ void red_add_v4(float* p, float a, float b, float c, float d) {
    asm volatile("red.global.add.v4.f32 [%0], {%1,%2,%3,%4};"
                 :: "l"(p), "f"(a), "f"(b), "f"(c), "f"(d) : "memory");
}

// ---------------- edge pass layer 1: one warp per edge (row = 128 floats) ----------------
__global__ __launch_bounds__(256) void edge1_kernel(int E) {
    int gt = blockIdx.x * 256 + threadIdx.x;
    int e = gt >> 5;
    if (e >= E) return;
    int lane = gt & 31;
    int src = __ldg(&g_src[e]);
    int dst = __ldg(&g_dst[e]);
    int head = lane >> 3;
    // score loads issued by group leader only, broadcast via shfl
    float sc = 0.f;
    if ((lane & 7) == 0)
        sc = g_as1[src * H + head] + g_ad1[dst * H + head];
    sc = __shfl_sync(0xffffffffu, sc, head * 8);
    sc = sc > 0.f ? sc : NEG * sc;
    float ex = __expf(sc);
    if ((lane & 7) == 0) atomicAdd(&g_denom1[dst * H + head], ex);
    float4 v = *(const float4*)&g_h1[src * 128 + lane * 4];
    red_add_v4(&g_accum1[dst * 128 + lane * 4], ex * v.x, ex * v.y, ex * v.z, ex * v.w);
}

// ---------------- edge pass layer 2: 16 lanes per edge (row = 64 floats) ----------------
__global__ __launch_bounds__(256) void edge2_kernel(int E) {
    int gt = blockIdx.x * 256 + threadIdx.x;
    int e = gt >> 4;
    if (e >= E) return;
    int lane = gt & 15;
    int half = (threadIdx.x & 31) >> 4;  // which 16-lane half of the warp
    int src = __ldg(&g_src[e]);
    int dst = __ldg(&g_dst[e]);
    int head = lane >> 2;
    float sc = 0.f;
    if ((lane & 3) == 0)
        sc = g_as2[src * H + head] + g_ad2[dst * H + head];
    sc = __shfl_sync(0xffffffffu, sc, half * 16 + head * 4);
    sc = sc > 0.f ? sc : NEG * sc;
    float ex = __expf(sc);
    if ((lane & 3) == 0) atomicAdd(&g_denom2[dst * H + head], ex);
    float4 v = *(const float4*)&g_h2[src * 64 + lane * 4];
    red_add_v4(&g_accum2[dst * 64 + lane * 4], ex * v.x, ex * v.y, ex * v.z, ex * v.w);
}

// ---------------- finalize layer 1: mean over heads + b1, ReLU -> g_x2 ----------------
__global__ void fin1_kernel(const float* __restrict__ b, int N) {
    int i = blockIdx.x * blockDim.x + threadIdx.x;
    if (i >= N * 32) return;
    int n = i >> 5, f = i & 31;
    float s = 0.f;
#pragma unroll
    for (int hh = 0; hh < 4; hh++)
        s += g_accum1[n * 128 + hh * 32 + f] / (g_denom1[n * 4 + hh] + EPSF);
    s = 0.25f * s + b[f];
    g_x2[i] = s > 0.f ? s : 0.f;
}

// ---------------- finalize layer 2: mean over heads + b2 -> out ----------------
__global__ void fin2_kernel(const float* __restrict__ b, float* __restrict__ out, int N) {
    int i = blockIdx.x * blockDim.x + threadIdx.x;
    if (i >= N * 16) return;
    int n = i >> 4, f = i & 15;
    float s = 0.f;
#pragma unroll
    for (int hh = 0; hh < 4; hh++)
        s += g_accum2[n * 64 + hh * 16 + f] / (g_denom2[n * 4 + hh] + EPSF);
    out[i] = 0.25f * s + b[f];
}

extern "C" void kernel_launch(void* const* d_in, const int* in_sizes, int n_in,
                              void* d_out, int out_size) {
    const float* x = (const float*)d_in[0];
    const void* ei = d_in[1];
    const float* W1 = (const float*)d_in[2];
    const float* a1s = (const float*)d_in[3];
    const float* a1d = (const float*)d_in[4];
    const float* b1 = (const float*)d_in[5];
    const float* W2 = (const float*)d_in[6];
    const float* a2s = (const float*)d_in[7];
    const float* a2d = (const float*)d_in[8];
    const float* b2 = (const float*)d_in[9];
    int N = in_sizes[0] / 128;
    int E = in_sizes[1] / 2;
    if (N > MAXN) N = MAXN;
    if (E > MAXE) E = MAXE;
    float* out = (float*)d_out;

    detect_kernel<<<1, 32>>>((const int*)ei);
    decode_kernel<<<(E + 255) / 256, 256>>>(ei, E, N);
    zero_kernel<<<1024, 256>>>(N);
    gemm1_kernel<<<(N + 31) / 32, 256>>>(x, W1, N);
    attn_kernel<32, 1><<<(N * 4 + 255) / 256, 256>>>(a1s, a1d, N);
    {
        long long threads = (long long)E * 32;
        edge1_kernel<<<(unsigned)((threads + 255) / 256), 256>>>(E);
    }
    fin1_kernel<<<(N * 32 + 255) / 256, 256>>>(b1, N);
    gemm2_kernel<<<(N + 63) / 64, 256>>>(W2, N);
    attn_kernel<16, 2><<<(N * 4 + 255) / 256, 256>>>(a2s, a2d, N);
    {
        long long threads = (long long)E * 16;
        edge2_kernel<<<(unsigned)((threads + 255) / 256), 256>>>(E);
    }
    fin2_kernel<<<(N * 16 + 255) / 256, 256>>>(b2, out, N);
}

// round 5
// speedup vs baseline: 2.3824x; 2.3824x over previous
#include <cuda_runtime.h>

#define H 4
#define MAXN 100000
#define MAXE 1000000
#define NEG 0.2f
#define EPSF 1e-16f
#define SCAN_NB ((MAXN + 255) / 256)

// ---------------- scratch (device globals; no allocation allowed) ----------------
__device__ __align__(16) float g_h1[MAXN * 128];  // layer1 features [N, H*32]
__device__ __align__(16) float g_as1[MAXN * H];
__device__ __align__(16) float g_ad1[MAXN * H];
__device__ __align__(16) float g_x2[MAXN * 32];   // relu(layer1 out)
__device__ __align__(16) float g_h2[MAXN * 64];   // layer2 features [N, H*16]
__device__ __align__(16) float g_as2[MAXN * H];
__device__ __align__(16) float g_ad2[MAXN * H];
__device__ int g_src[MAXE];
__device__ int g_dst[MAXE];
__device__ int g_csr_src[MAXE];
__device__ int g_deg[MAXN];
__device__ int g_rowptr[MAXN + 1];
__device__ int g_wpos[MAXN];
__device__ int g_bsum[SCAN_NB];
__device__ int g_bscan[SCAN_NB];
__device__ int g_is64;

// ---------------- dtype sniffer: int64 edge_index has zero high words ----------------
__global__ void detect_kernel(const int* __restrict__ ei_raw) {
    if (threadIdx.x == 0 && blockIdx.x == 0) {
        int all0 = 1;
        for (int i = 0; i < 32; i++)
            if (ei_raw[2 * i + 1] != 0) { all0 = 0; break; }
        g_is64 = all0;
    }
}

// ---------------- decode edge list to int32 (clamped), zero deg ----------------
__global__ void decode_kernel(const void* __restrict__ ei, int E, int N) {
    int e = blockIdx.x * blockDim.x + threadIdx.x;
    if (e < N) g_deg[e] = 0;
    if (e >= E) return;
    int s, d;
    if (g_is64) {
        s = (int)((const long long*)ei)[e];
        d = (int)((const long long*)ei)[E + e];
    } else {
        s = ((const int*)ei)[e];
        d = ((const int*)ei)[E + e];
    }
    s = s < 0 ? 0 : (s >= N ? N - 1 : s);
    d = d < 0 ? 0 : (d >= N ? N - 1 : d);
    g_src[e] = s;
    g_dst[e] = d;
}

__global__ void count_kernel(int E) {
    int e = blockIdx.x * blockDim.x + threadIdx.x;
    if (e < E) atomicAdd(&g_deg[g_dst[e]], 1);
}

// ---------------- 3-kernel exclusive scan of g_deg -> g_rowptr ----------------
__global__ void scan1_kernel(int N) {
    __shared__ int s[256];
    int t = threadIdx.x;
    int i = blockIdx.x * 256 + t;
    int v = (i < N) ? g_deg[i] : 0;
    s[t] = v;
    for (int off = 1; off < 256; off <<= 1) {
        __syncthreads();
        int tv = (t >= off) ? s[t - off] : 0;
        __syncthreads();
        s[t] += tv;
    }
    __syncthreads();
    if (i < N) g_rowptr[i] = s[t] - v;  // local exclusive
    if (t == 255) g_bsum[blockIdx.x] = s[255];
}

__global__ void scan2_kernel(int nb) {
    __shared__ int s[512];
    int t = threadIdx.x;
    int v = (t < nb) ? g_bsum[t] : 0;
    s[t] = v;
    for (int off = 1; off < 512; off <<= 1) {
        __syncthreads();
        int tv = (t >= off) ? s[t - off] : 0;
        __syncthreads();
        s[t] += tv;
    }
    __syncthreads();
    if (t < nb) g_bscan[t] = s[t] - v;  // exclusive
}

__global__ void scan3_kernel(int N, int E) {
    int i = blockIdx.x * blockDim.x + threadIdx.x;
    if (i < N) {
        int r = g_rowptr[i] + g_bscan[i >> 8];
        g_rowptr[i] = r;
        g_wpos[i] = r;
    }
    if (i == 0) g_rowptr[N] = E;
}

__global__ void scatter_kernel(int E) {
    int e = blockIdx.x * blockDim.x + threadIdx.x;
    if (e >= E) return;
    int d = g_dst[e];
    int p = atomicAdd(&g_wpos[d], 1);
    g_csr_src[p] = g_src[e];
}

// ---------------- GEMM1: h1[N,128] = x[N,128] @ W1[128,128]; 8x4 per thread ----------------
__global__ __launch_bounds__(256) void gemm1_kernel(const float* __restrict__ x,
                                                    const float* __restrict__ W, int N) {
    __shared__ __align__(16) float xs[64][33];
    __shared__ __align__(16) float ws[32][128];
    int tid = threadIdx.x;
    int cg = tid & 31;      // cols 4*cg..4*cg+3
    int rs = tid >> 5;      // 0..7; rows rs + 8*j
    int rowbase = blockIdx.x * 64;
    float4 acc[8];
#pragma unroll
    for (int j = 0; j < 8; j++) acc[j] = make_float4(0.f, 0.f, 0.f, 0.f);
    for (int k0 = 0; k0 < 128; k0 += 32) {
#pragma unroll
        for (int i = 0; i < 2; i++) {
            int idx = tid + i * 256;  // 0..511
            int r = idx >> 3, kq = idx & 7;
            int row = rowbase + r;
            float4 v = make_float4(0.f, 0.f, 0.f, 0.f);
            if (row < N) v = *(const float4*)&x[row * 128 + k0 + kq * 4];
            xs[r][kq * 4 + 0] = v.x; xs[r][kq * 4 + 1] = v.y;
            xs[r][kq * 4 + 2] = v.z; xs[r][kq * 4 + 3] = v.w;
        }
#pragma unroll
        for (int i = 0; i < 4; i++) {
            int idx = tid + i * 256;
            int k = idx >> 5, c = idx & 31;
            *(float4*)&ws[k][c * 4] = *(const float4*)&W[(k0 + k) * 128 + c * 4];
        }
        __syncthreads();
#pragma unroll
        for (int k = 0; k < 32; k++) {
            float4 w = *(const float4*)&ws[k][cg * 4];
#pragma unroll
            for (int j = 0; j < 8; j++) {
                float xv = xs[rs + 8 * j][k];
                acc[j].x += xv * w.x; acc[j].y += xv * w.y;
                acc[j].z += xv * w.z; acc[j].w += xv * w.w;
            }
        }
        __syncthreads();
    }
#pragma unroll
    for (int j = 0; j < 8; j++) {
        int row = rowbase + rs + 8 * j;
        if (row < N) *(float4*)&g_h1[row * 128 + cg * 4] = acc[j];
    }
}

// ---------------- GEMM2: h2[N,64] = x2[N,32] @ W2[32,64] ----------------
__global__ __launch_bounds__(256) void gemm2_kernel(const float* __restrict__ W, int N) {
    __shared__ __align__(16) float xs[64][33];
    __shared__ __align__(16) float ws[32][64];
    int tid = threadIdx.x;
    int cg = tid & 15;
    int rowslot = tid >> 4;
    int rowbase = blockIdx.x * 64;
#pragma unroll
    for (int i = 0; i < 2; i++) {
        int idx = tid + i * 256;
        int k = idx >> 4, c = idx & 15;
        *(float4*)&ws[k][c * 4] = *(const float4*)&W[k * 64 + c * 4];
    }
#pragma unroll
    for (int i = 0; i < 2; i++) {
        int idx = tid + i * 256;
        int r = idx >> 3, kq = idx & 7;
        int row = rowbase + r;
        float4 v = make_float4(0.f, 0.f, 0.f, 0.f);
        if (row < N) v = *(const float4*)&g_x2[row * 32 + kq * 4];
        xs[r][kq * 4 + 0] = v.x; xs[r][kq * 4 + 1] = v.y;
        xs[r][kq * 4 + 2] = v.z; xs[r][kq * 4 + 3] = v.w;
    }
    __syncthreads();
    float4 acc[4];
#pragma unroll
    for (int j = 0; j < 4; j++) acc[j] = make_float4(0.f, 0.f, 0.f, 0.f);
#pragma unroll
    for (int k = 0; k < 32; k++) {
        float4 w = *(const float4*)&ws[k][cg * 4];
#pragma unroll
        for (int j = 0; j < 4; j++) {
            float xv = xs[rowslot + 16 * j][k];
            acc[j].x += xv * w.x; acc[j].y += xv * w.y;
            acc[j].z += xv * w.z; acc[j].w += xv * w.w;
        }
    }
#pragma unroll
    for (int j = 0; j < 4; j++) {
        int row = rowbase + rowslot + 16 * j;
        if (row < N) *(float4*)&g_h2[row * 64 + cg * 4] = acc[j];
    }
}

// ---------------- per-node attention halves: as/ad ----------------
template <int F, int LAYER>
__global__ __launch_bounds__(256) void attn_kernel(const float* __restrict__ a_src,
                                                   const float* __restrict__ a_dst, int N) {
    int i = blockIdx.x * blockDim.x + threadIdx.x;
    if (i >= N * H) return;
    int hh = i & 3;
    const float* h = (LAYER == 1) ? g_h1 : g_h2;
    float* as_ = (LAYER == 1) ? g_as1 : g_as2;
    float* ad_ = (LAYER == 1) ? g_ad1 : g_ad2;
    const float* row = h + (size_t)i * F;
    const float* av = a_src + hh * F;
    const float* bv = a_dst + hh * F;
    float s = 0.f, d = 0.f;
#pragma unroll
    for (int f = 0; f < F; f += 4) {
        float4 hv = *(const float4*)&row[f];
        float4 a1 = *(const float4*)&av[f];
        float4 a2 = *(const float4*)&bv[f];
        s += hv.x * a1.x + hv.y * a1.y + hv.z * a1.z + hv.w * a1.w;
        d += hv.x * a2.x + hv.y * a2.y + hv.z * a2.z + hv.w * a2.w;
    }
    as_[i] = s;
    ad_[i] = d;
}

// ---------------- gather layer 1: warp per dst; fused softmax-div + head-mean + bias + relu ----------------
__global__ __launch_bounds__(256) void gather1_kernel(const float* __restrict__ b, int N) {
    int gt = blockIdx.x * 256 + threadIdx.x;
    int d = gt >> 5;
    if (d >= N) return;
    int lane = gt & 31;
    int head = lane >> 3;
    int beg = g_rowptr[d], end = g_rowptr[d + 1];
    float adh = g_ad1[d * 4 + head];
    float4 acc = make_float4(0.f, 0.f, 0.f, 0.f);
    float dsum = 0.f;
    for (int j = beg; j < end; j++) {
        int s = g_csr_src[j];
        float sc = g_as1[s * 4 + head] + adh;
        sc = sc > 0.f ? sc : NEG * sc;
        float ex = __expf(sc);
        float4 v = *(const float4*)&g_h1[s * 128 + lane * 4];
        acc.x += ex * v.x; acc.y += ex * v.y;
        acc.z += ex * v.z; acc.w += ex * v.w;
        dsum += ex;
    }
    float inv = 1.f / (dsum + EPSF);
    acc.x *= inv; acc.y *= inv; acc.z *= inv; acc.w *= inv;
    // butterfly-sum across the 4 head groups (lanes differing in bits 3,4)
#pragma unroll
    for (int m = 8; m <= 16; m <<= 1) {
        acc.x += __shfl_xor_sync(0xffffffffu, acc.x, m);
        acc.y += __shfl_xor_sync(0xffffffffu, acc.y, m);
        acc.z += __shfl_xor_sync(0xffffffffu, acc.z, m);
        acc.w += __shfl_xor_sync(0xffffffffu, acc.w, m);
    }
    if (lane < 8) {
        float4 bb = *(const float4*)&b[lane * 4];
        float4 o;
        o.x = 0.25f * acc.x + bb.x; o.y = 0.25f * acc.y + bb.y;
        o.z = 0.25f * acc.z + bb.z; o.w = 0.25f * acc.w + bb.w;
        o.x = o.x > 0.f ? o.x : 0.f; o.y = o.y > 0.f ? o.y : 0.f;
        o.z = o.z > 0.f ? o.z : 0.f; o.w = o.w > 0.f ? o.w : 0.f;
        *(float4*)&g_x2[d * 32 + lane * 4] = o;
    }
}

// ---------------- gather layer 2: warp per dst; write final output ----------------
__global__ __launch_bounds__(256) void gather2_kernel(const float* __restrict__ b,
                                                      float* __restrict__ out, int N) {
    int gt = blockIdx.x * 256 + threadIdx.x;
    int d = gt >> 5;
    if (d >= N) return;
    int lane = gt & 31;
    int head = lane >> 3;  // feature pair (lane&7)*2 within head
    int beg = g_rowptr[d], end = g_rowptr[d + 1];
    float adh = g_ad2[d * 4 + head];
    float2 acc = make_float2(0.f, 0.f);
    float dsum = 0.f;
    for (int j = beg; j < end; j++) {
        int s = g_csr_src[j];
        float sc = g_as2[s * 4 + head] + adh;
        sc = sc > 0.f ? sc : NEG * sc;
        float ex = __expf(sc);
        float2 v = *(const float2*)&g_h2[s * 64 + lane * 2];
        acc.x += ex * v.x; acc.y += ex * v.y;
        dsum += ex;
    }
    float inv = 1.f / (dsum + EPSF);
    acc.x *= inv; acc.y *= inv;
#pragma unroll
    for (int m = 8; m <= 16; m <<= 1) {
        acc.x += __shfl_xor_sync(0xffffffffu, acc.x, m);
        acc.y += __shfl_xor_sync(0xffffffffu, acc.y, m);
    }
    if (lane < 8) {
        float2 bb = *(const float2*)&b[lane * 2];
        float2 o;
        o.x = 0.25f * acc.x + bb.x;
        o.y = 0.25f * acc.y + bb.y;
        *(float2*)&out[d * 16 + lane * 2] = o;
    }
}

extern "C" void kernel_launch(void* const* d_in, const int* in_sizes, int n_in,
                              void* d_out, int out_size) {
    const float* x = (const float*)d_in[0];
    const void* ei = d_in[1];
    const float* W1 = (const float*)d_in[2];
    const float* a1s = (const float*)d_in[3];
    const float* a1d = (const float*)d_in[4];
    const float* b1 = (const float*)d_in[5];
    const float* W2 = (const float*)d_in[6];
    const float* a2s = (const float*)d_in[7];
    const float* a2d = (const float*)d_in[8];
    const float* b2 = (const float*)d_in[9];
    int N = in_sizes[0] / 128;
    int E = in_sizes[1] / 2;
    if (N > MAXN) N = MAXN;
    if (E > MAXE) E = MAXE;
    float* out = (float*)d_out;
    int nb = (N + 255) / 256;
    int grid_e = (E + 255) / 256;
    int grid_warp = (N * 32 + 255) / 256;

    detect_kernel<<<1, 32>>>((const int*)ei);
    decode_kernel<<<grid_e, 256>>>(ei, E, N);
    count_kernel<<<grid_e, 256>>>(E);
    scan1_kernel<<<nb, 256>>>(N);
    scan2_kernel<<<1, 512>>>(nb);
    scan3_kernel<<<nb, 256>>>(N, E);
    scatter_kernel<<<grid_e, 256>>>(E);

    gemm1_kernel<<<(N + 63) / 64, 256>>>(x, W1, N);
    attn_kernel<32, 1><<<(N * 4 + 255) / 256, 256>>>(a1s, a1d, N);
    gather1_kernel<<<grid_warp, 256>>>(b1, N);

    gemm2_kernel<<<(N + 63) / 64, 256>>>(W2, N);
    attn_kernel<16, 2><<<(N * 4 + 255) / 256, 256>>>(a2s, a2d, N);
    gather2_kernel<<<grid_warp, 256>>>(b2, out, N);
}

// round 8
// speedup vs baseline: 2.8458x; 1.1945x over previous
#include <cuda_runtime.h>
#include <cuda_fp16.h>
#include <cuda_bf16.h>
#include <cstdint>

#define H 4
#define MAXN 100000
#define MAXE 1000000
#define NEG 0.2f
#define EPSF 1e-16f
#define SCAN_NB ((MAXN + 255) / 256)

// ---------------- scratch (device globals; no allocation allowed) ----------------
__device__ __align__(16) __half g_h1h[MAXN * 128];          // layer1 features fp16
__device__ __align__(16) __half g_h2h[MAXN * 64];           // layer2 features fp16
__device__ __align__(16) __nv_bfloat16 g_xhi[MAXN * 128];   // x split for tensor gemm
__device__ __align__(16) __nv_bfloat16 g_xlo[MAXN * 128];
__device__ __align__(16) __nv_bfloat16 g_w1thi[128 * 128];  // W1^T split [n][k]
__device__ __align__(16) __nv_bfloat16 g_w1tlo[128 * 128];
__device__ __align__(16) __nv_bfloat16 g_x2hi[MAXN * 32];   // layer1 output split
__device__ __align__(16) __nv_bfloat16 g_x2lo[MAXN * 32];
__device__ __align__(16) __nv_bfloat16 g_w2thi[64 * 32];    // W2^T split [n][k]
__device__ __align__(16) __nv_bfloat16 g_w2tlo[64 * 32];
__device__ __align__(16) float g_as1[MAXN * H];
__device__ __align__(16) float g_ad1[MAXN * H];
__device__ __align__(16) float g_as2[MAXN * H];
__device__ __align__(16) float g_ad2[MAXN * H];
__device__ int g_src[MAXE];
__device__ int g_dst[MAXE];
__device__ int g_csr_src[MAXE];
__device__ int g_deg[MAXN];
__device__ int g_rowptr[MAXN + 1];
__device__ int g_wpos[MAXN];
__device__ int g_bsum[SCAN_NB];
__device__ int g_bscan[SCAN_NB];
__device__ int g_is64;

// ---------------- dtype sniffer ----------------
__global__ void detect_kernel(const int* __restrict__ ei_raw) {
    if (threadIdx.x == 0 && blockIdx.x == 0) {
        int all0 = 1;
        for (int i = 0; i < 32; i++)
            if (ei_raw[2 * i + 1] != 0) { all0 = 0; break; }
        g_is64 = all0;
    }
}

__global__ void zdeg_kernel(int N) {
    int i = blockIdx.x * blockDim.x + threadIdx.x;
    if (i < N) g_deg[i] = 0;
}

// ---------------- decode + degree count fused ----------------
__global__ void decode_count_kernel(const void* __restrict__ ei, int E, int N) {
    int e = blockIdx.x * blockDim.x + threadIdx.x;
    if (e >= E) return;
    int s, d;
    if (g_is64) {
        s = (int)((const long long*)ei)[e];
        d = (int)((const long long*)ei)[E + e];
    } else {
        s = ((const int*)ei)[e];
        d = ((const int*)ei)[E + e];
    }
    s = s < 0 ? 0 : (s >= N ? N - 1 : s);
    d = d < 0 ? 0 : (d >= N ? N - 1 : d);
    g_src[e] = s;
    g_dst[e] = d;
    atomicAdd(&g_deg[d], 1);
}

// ---------------- 3-kernel exclusive scan of g_deg -> g_rowptr ----------------
__global__ void scan1_kernel(int N) {
    __shared__ int s[256];
    int t = threadIdx.x;
    int i = blockIdx.x * 256 + t;
    int v = (i < N) ? g_deg[i] : 0;
    s[t] = v;
    for (int off = 1; off < 256; off <<= 1) {
        __syncthreads();
        int tv = (t >= off) ? s[t - off] : 0;
        __syncthreads();
        s[t] += tv;
    }
    __syncthreads();
    if (i < N) g_rowptr[i] = s[t] - v;
    if (t == 255) g_bsum[blockIdx.x] = s[255];
}

__global__ void scan2_kernel(int nb) {
    __shared__ int s[512];
    int t = threadIdx.x;
    int v = (t < nb) ? g_bsum[t] : 0;
    s[t] = v;
    for (int off = 1; off < 512; off <<= 1) {
        __syncthreads();
        int tv = (t >= off) ? s[t - off] : 0;
        __syncthreads();
        s[t] += tv;
    }
    __syncthreads();
    if (t < nb) g_bscan[t] = s[t] - v;
}

__global__ void scan3_kernel(int N, int E) {
    int i = blockIdx.x * blockDim.x + threadIdx.x;
    if (i < N) {
        int r = g_rowptr[i] + g_bscan[i >> 8];
        g_rowptr[i] = r;
        g_wpos[i] = r;
    }
    if (i == 0) g_rowptr[N] = E;
}

__global__ void scatter_kernel(int E) {
    int e = blockIdx.x * blockDim.x + threadIdx.x;
    if (e >= E) return;
    int d = g_dst[e];
    int p = atomicAdd(&g_wpos[d], 1);
    g_csr_src[p] = g_src[e];
}

// ---------------- convert x, W1^T, W2^T to bf16 hi/lo ----------------
__global__ void convert_kernel(const float* __restrict__ x,
                               const float* __restrict__ W1,
                               const float* __restrict__ W2, int N) {
    int nx = N * 32;  // float4 count for x
    int total = nx + 128 * 128 + 32 * 64;
    int stride = gridDim.x * blockDim.x;
    for (int i = blockIdx.x * blockDim.x + threadIdx.x; i < total; i += stride) {
        if (i < nx) {
            float4 v = ((const float4*)x)[i];
            __nv_bfloat16 h0 = __float2bfloat16(v.x), h1 = __float2bfloat16(v.y);
            __nv_bfloat16 h2 = __float2bfloat16(v.z), h3 = __float2bfloat16(v.w);
            __nv_bfloat16 l0 = __float2bfloat16(v.x - __bfloat162float(h0));
            __nv_bfloat16 l1 = __float2bfloat16(v.y - __bfloat162float(h1));
            __nv_bfloat16 l2 = __float2bfloat16(v.z - __bfloat162float(h2));
            __nv_bfloat16 l3 = __float2bfloat16(v.w - __bfloat162float(h3));
            ((__nv_bfloat162*)g_xhi)[i * 2 + 0] = __halves2bfloat162(h0, h1);
            ((__nv_bfloat162*)g_xhi)[i * 2 + 1] = __halves2bfloat162(h2, h3);
            ((__nv_bfloat162*)g_xlo)[i * 2 + 0] = __halves2bfloat162(l0, l1);
            ((__nv_bfloat162*)g_xlo)[i * 2 + 1] = __halves2bfloat162(l2, l3);
        } else if (i < nx + 128 * 128) {
            int t = i - nx;
            int k = t >> 7, n = t & 127;
            float a = W1[k * 128 + n];
            __nv_bfloat16 hv = __float2bfloat16(a);
            g_w1thi[n * 128 + k] = hv;
            g_w1tlo[n * 128 + k] = __float2bfloat16(a - __bfloat162float(hv));
        } else {
            int t = i - nx - 128 * 128;
            int k = t >> 6, n = t & 63;
            float a = W2[k * 64 + n];
            __nv_bfloat16 hv = __float2bfloat16(a);
            g_w2thi[n * 32 + k] = hv;
            g_w2tlo[n * 32 + k] = __float2bfloat16(a - __bfloat162float(hv));
        }
    }
}

// ---------------- bf16 mma helper ----------------
__device__ __forceinline__ void mma_bf16(float* c, uint32_t a0, uint32_t a1,
                                         uint32_t a2, uint32_t a3,
                                         uint32_t b0, uint32_t b1) {
    asm volatile(
        "mma.sync.aligned.m16n8k16.row.col.f32.bf16.bf16.f32 "
        "{%0,%1,%2,%3}, {%4,%5,%6,%7}, {%8,%9}, {%0,%1,%2,%3};\n"
        : "+f"(c[0]), "+f"(c[1]), "+f"(c[2]), "+f"(c[3])
        : "r"(a0), "r"(a1), "r"(a2), "r"(a3), "r"(b0), "r"(b1));
}

// ---------------- GEMM1 (tensor): h1h[N,128] = x[N,128] @ W1 via bf16x3 ----------------
__global__ __launch_bounds__(256) void gemm1_tc_kernel(int N) {
    __shared__ uint32_t As[2][128][8];  // [part][row][kpair]
    __shared__ uint32_t Bs[2][128][8];  // [part][n][kpair]
    int tid = threadIdx.x;
    int lane = tid & 31, wid = tid >> 5;
    int gid = lane >> 2, tig = lane & 3;
    int wm = (wid >> 1) * 32, wn = (wid & 1) * 64;
    int rowbase = blockIdx.x * 128;
    float c[2][8][4];
#pragma unroll
    for (int mt = 0; mt < 2; mt++)
#pragma unroll
        for (int nt = 0; nt < 8; nt++)
#pragma unroll
            for (int r = 0; r < 4; r++) c[mt][nt][r] = 0.f;

    for (int k0 = 0; k0 < 128; k0 += 16) {
#pragma unroll
        for (int i = 0; i < 2; i++) {  // A tile
            int cc = tid + i * 256;            // 0..511
            int part = cc >> 8, rem = cc & 255;
            int row = rem >> 1, hf = (rem & 1) * 4;
            const __nv_bfloat16* sp = part ? g_xlo : g_xhi;
            int grow = rowbase + row;
            uint4 v = make_uint4(0u, 0u, 0u, 0u);
            if (grow < N) v = *(const uint4*)&sp[grow * 128 + k0 + hf * 2];
            *(uint4*)&As[part][row][hf] = v;
        }
#pragma unroll
        for (int i = 0; i < 2; i++) {  // B tile
            int cc = tid + i * 256;
            int part = cc >> 8, rem = cc & 255;
            int n = rem >> 1, hf = (rem & 1) * 4;
            const __nv_bfloat16* sp = part ? g_w1tlo : g_w1thi;
            *(uint4*)&Bs[part][n][hf] = *(const uint4*)&sp[n * 128 + k0 + hf * 2];
        }
        __syncthreads();
        uint32_t af[2][2][4];
#pragma unroll
        for (int p = 0; p < 2; p++)
#pragma unroll
            for (int mt = 0; mt < 2; mt++) {
                int r = wm + mt * 16 + gid;
                af[p][mt][0] = As[p][r][tig];
                af[p][mt][1] = As[p][r + 8][tig];
                af[p][mt][2] = As[p][r][tig + 4];
                af[p][mt][3] = As[p][r + 8][tig + 4];
            }
#pragma unroll
        for (int combo = 0; combo < 3; combo++) {
            int pa = (combo == 2) ? 1 : 0;
            int pb = (combo == 1) ? 1 : 0;
#pragma unroll
            for (int nt = 0; nt < 8; nt++) {
                int nr = wn + nt * 8 + gid;
                uint32_t b0 = Bs[pb][nr][tig];
                uint32_t b1 = Bs[pb][nr][tig + 4];
                mma_bf16(c[0][nt], af[pa][0][0], af[pa][0][1], af[pa][0][2], af[pa][0][3], b0, b1);
                mma_bf16(c[1][nt], af[pa][1][0], af[pa][1][1], af[pa][1][2], af[pa][1][3], b0, b1);
            }
        }
        __syncthreads();
    }
#pragma unroll
    for (int mt = 0; mt < 2; mt++)
#pragma unroll
        for (int nt = 0; nt < 8; nt++) {
            int row = rowbase + wm + mt * 16 + gid;
            int col = wn + nt * 8 + tig * 2;
            if (row < N)
                *(__half2*)&g_h1h[row * 128 + col] = __floats2half2_rn(c[mt][nt][0], c[mt][nt][1]);
            if (row + 8 < N)
                *(__half2*)&g_h1h[(row + 8) * 128 + col] = __floats2half2_rn(c[mt][nt][2], c[mt][nt][3]);
        }
}

// ---------------- GEMM2 (tensor): h2h[N,64] = x2[N,32] @ W2 via bf16x3 ----------------
__global__ __launch_bounds__(256) void gemm2_tc_kernel(int N) {
    __shared__ uint32_t As[2][128][16];  // K=32 -> 16 pairs
    __shared__ uint32_t Bs[2][64][16];
    int tid = threadIdx.x;
    int lane = tid & 31, wid = tid >> 5;
    int gid = lane >> 2, tig = lane & 3;
    int wm = (wid >> 1) * 32, wn = (wid & 1) * 32;
    int rowbase = blockIdx.x * 128;
    float c[2][4][4];
#pragma unroll
    for (int mt = 0; mt < 2; mt++)
#pragma unroll
        for (int nt = 0; nt < 4; nt++)
#pragma unroll
            for (int r = 0; r < 4; r++) c[mt][nt][r] = 0.f;
#pragma unroll
    for (int i = 0; i < 4; i++) {  // A tile: 1024 chunks of 16B
        int cc = tid + i * 256;
        int part = cc >> 9, rem = cc & 511;
        int row = rem >> 2, hf = (rem & 3) * 4;
        const __nv_bfloat16* sp = part ? g_x2lo : g_x2hi;
        int grow = rowbase + row;
        uint4 v = make_uint4(0u, 0u, 0u, 0u);
        if (grow < N) v = *(const uint4*)&sp[grow * 32 + hf * 2];
        *(uint4*)&As[part][row][hf] = v;
    }
#pragma unroll
    for (int i = 0; i < 2; i++) {  // B tile: 512 chunks
        int cc = tid + i * 256;
        int part = cc >> 8, rem = cc & 255;
        int n = rem >> 2, hf = (rem & 3) * 4;
        const __nv_bfloat16* sp = part ? g_w2tlo : g_w2thi;
        *(uint4*)&Bs[part][n][hf] = *(const uint4*)&sp[n * 32 + hf * 2];
    }
    __syncthreads();
#pragma unroll
    for (int kc = 0; kc < 2; kc++) {
        uint32_t af[2][2][4];
#pragma unroll
        for (int p = 0; p < 2; p++)
#pragma unroll
            for (int mt = 0; mt < 2; mt++) {
                int r = wm + mt * 16 + gid;
                af[p][mt][0] = As[p][r][tig + kc * 8];
                af[p][mt][1] = As[p][r + 8][tig + kc * 8];
                af[p][mt][2] = As[p][r][tig + 4 + kc * 8];
                af[p][mt][3] = As[p][r + 8][tig + 4 + kc * 8];
            }
#pragma unroll
        for (int combo = 0; combo < 3; combo++) {
            int pa = (combo == 2) ? 1 : 0;
            int pb = (combo == 1) ? 1 : 0;
#pragma unroll
            for (int nt = 0; nt < 4; nt++) {
                int nr = wn + nt * 8 + gid;
                uint32_t b0 = Bs[pb][nr][tig + kc * 8];
                uint32_t b1 = Bs[pb][nr][tig + 4 + kc * 8];
                mma_bf16(c[0][nt], af[pa][0][0], af[pa][0][1], af[pa][0][2], af[pa][0][3], b0, b1);
                mma_bf16(c[1][nt], af[pa][1][0], af[pa][1][1], af[pa][1][2], af[pa][1][3], b0, b1);
            }
        }
    }
#pragma unroll
    for (int mt = 0; mt < 2; mt++)
#pragma unroll
        for (int nt = 0; nt < 4; nt++) {
            int row = rowbase + wm + mt * 16 + gid;
            int col = wn + nt * 8 + tig * 2;
            if (row < N)
                *(__half2*)&g_h2h[row * 64 + col] = __floats2half2_rn(c[mt][nt][0], c[mt][nt][1]);
            if (row + 8 < N)
                *(__half2*)&g_h2h[(row + 8) * 64 + col] = __floats2half2_rn(c[mt][nt][2], c[mt][nt][3]);
        }
}

// ---------------- per-node attention halves ----------------
template <int F, int LAYER>
__global__ __launch_bounds__(256) void attn_kernel(const float* __restrict__ a_src,
                                                   const float* __restrict__ a_dst, int N) {
    int i = blockIdx.x * blockDim.x + threadIdx.x;
    if (i >= N * H) return;
    int hh = i & 3;
    const __half* h = (LAYER == 1) ? g_h1h : g_h2h;
    float* as_ = (LAYER == 1) ? g_as1 : g_as2;
    float* ad_ = (LAYER == 1) ? g_ad1 : g_ad2;
    const __half* row = h + (size_t)i * F;
    const float* av = a_src + hh * F;
    const float* bv = a_dst + hh * F;
    float s = 0.f, d = 0.f;
#pragma unroll
    for (int f = 0; f < F; f += 2) {
        float2 hv = __half22float2(*(const __half2*)&row[f]);
        s += hv.x * av[f] + hv.y * av[f + 1];
        d += hv.x * bv[f] + hv.y * bv[f + 1];
    }
    as_[i] = s;
    ad_[i] = d;
}

// ---------------- gather layer 1: warp/dst; fp16 rows; emits x2 bf16 hi/lo ----------------
__global__ __launch_bounds__(256) void gather1_kernel(const float* __restrict__ b, int N) {
    int gt = blockIdx.x * 256 + threadIdx.x;
    int d = gt >> 5;
    if (d >= N) return;
    int lane = gt & 31;
    int head = lane >> 3;
    int beg = g_rowptr[d], end = g_rowptr[d + 1];
    float adh = g_ad1[d * 4 + head];
    float a0 = 0.f, a1 = 0.f, a2 = 0.f, a3 = 0.f, dsum = 0.f;
    for (int j = beg; j < end; j++) {
        int s = g_csr_src[j];
        float sc = g_as1[s * 4 + head] + adh;
        sc = sc > 0.f ? sc : NEG * sc;
        float ex = __expf(sc);
        uint2 raw = *(const uint2*)&g_h1h[s * 128 + lane * 4];
        float2 f0 = __half22float2(*(__half2*)&raw.x);
        float2 f1 = __half22float2(*(__half2*)&raw.y);
        a0 += ex * f0.x; a1 += ex * f0.y; a2 += ex * f1.x; a3 += ex * f1.y;
        dsum += ex;
    }
    float inv = 1.f / (dsum + EPSF);
    a0 *= inv; a1 *= inv; a2 *= inv; a3 *= inv;
#pragma unroll
    for (int m = 8; m <= 16; m <<= 1) {
        a0 += __shfl_xor_sync(0xffffffffu, a0, m);
        a1 += __shfl_xor_sync(0xffffffffu, a1, m);
        a2 += __shfl_xor_sync(0xffffffffu, a2, m);
        a3 += __shfl_xor_sync(0xffffffffu, a3, m);
    }
    if (lane < 8) {
        float4 bb = *(const float4*)&b[lane * 4];
        float o0 = 0.25f * a0 + bb.x, o1 = 0.25f * a1 + bb.y;
        float o2 = 0.25f * a2 + bb.z, o3 = 0.25f * a3 + bb.w;
        o0 = o0 > 0.f ? o0 : 0.f; o1 = o1 > 0.f ? o1 : 0.f;
        o2 = o2 > 0.f ? o2 : 0.f; o3 = o3 > 0.f ? o3 : 0.f;
        __nv_bfloat16 h0 = __float2bfloat16(o0), h1 = __float2bfloat16(o1);
        __nv_bfloat16 h2 = __float2bfloat16(o2), h3 = __float2bfloat16(o3);
        __nv_bfloat16 l0 = __float2bfloat16(o0 - __bfloat162float(h0));
        __nv_bfloat16 l1 = __float2bfloat16(o1 - __bfloat162float(h1));
        __nv_bfloat16 l2 = __float2bfloat16(o2 - __bfloat162float(h2));
        __nv_bfloat16 l3 = __float2bfloat16(o3 - __bfloat162float(h3));
        int base = d * 32 + lane * 4;
        ((__nv_bfloat162*)&g_x2hi[base])[0] = __halves2bfloat162(h0, h1);
        ((__nv_bfloat162*)&g_x2hi[base])[1] = __halves2bfloat162(h2, h3);
        ((__nv_bfloat162*)&g_x2lo[base])[0] = __halves2bfloat162(l0, l1);
        ((__nv_bfloat162*)&g_x2lo[base])[1] = __halves2bfloat162(l2, l3);
    }
}

// ---------------- gather layer 2: warp/dst, 2 edges per iter; write output ----------------
__global__ __launch_bounds__(256) void gather2_kernel(const float* __restrict__ b,
                                                      float* __restrict__ out, int N) {
    int gt = blockIdx.x * 256 + threadIdx.x;
    int d = gt >> 5;
    if (d >= N) return;
    int lane = gt & 31;
    int sub = lane >> 4;      // edge parity
    int l = lane & 15;        // feats l*4..l*4+3
    int head = l >> 2;
    int beg = g_rowptr[d], end = g_rowptr[d + 1];
    float adh = g_ad2[d * 4 + head];
    float a0 = 0.f, a1 = 0.f, a2 = 0.f, a3 = 0.f, dsum = 0.f;
    for (int j = beg + sub; j < end; j += 2) {
        int s = g_csr_src[j];
        float sc = g_as2[s * 4 + head] + adh;
        sc = sc > 0.f ? sc : NEG * sc;
        float ex = __expf(sc);
        uint2 raw = *(const uint2*)&g_h2h[s * 64 + l * 4];
        float2 f0 = __half22float2(*(__half2*)&raw.x);
        float2 f1 = __half22float2(*(__half2*)&raw.y);
        a0 += ex * f0.x; a1 += ex * f0.y; a2 += ex * f1.x; a3 += ex * f1.y;
        dsum += ex;
    }
    // combine edge halves
    a0 += __shfl_xor_sync(0xffffffffu, a0, 16);
    a1 += __shfl_xor_sync(0xffffffffu, a1, 16);
    a2 += __shfl_xor_sync(0xffffffffu, a2, 16);
    a3 += __shfl_xor_sync(0xffffffffu, a3, 16);
    dsum += __shfl_xor_sync(0xffffffffu, dsum, 16);
    float inv = 1.f / (dsum + EPSF);
    a0 *= inv; a1 *= inv; a2 *= inv; a3 *= inv;
    // mean over heads (head bits 2,3 of l)
#pragma unroll
    for (int m = 4; m <= 8; m <<= 1) {
        a0 += __shfl_xor_sync(0xffffffffu, a0, m);
        a1 += __shfl_xor_sync(0xffffffffu, a1, m);
        a2 += __shfl_xor_sync(0xffffffffu, a2, m);
        a3 += __shfl_xor_sync(0xffffffffu, a3, m);
    }
    if (lane < 4) {
        float4 bb = *(const float4*)&b[lane * 4];
        float4 o;
        o.x = 0.25f * a0 + bb.x; o.y = 0.25f * a1 + bb.y;
        o.z = 0.25f * a2 + bb.z; o.w = 0.25f * a3 + bb.w;
        *(float4*)&out[d * 16 + lane * 4] = o;
    }
}

extern "C" void kernel_launch(void* const* d_in, const int* in_sizes, int n_in,
                              void* d_out, int out_size) {
    const float* x = (const float*)d_in[0];
    const void* ei = d_in[1];
    const float* W1 = (const float*)d_in[2];
    const float* a1s = (const float*)d_in[3];
    const float* a1d = (const float*)d_in[4];
    const float* b1 = (const float*)d_in[5];
    const float* W2 = (const float*)d_in[6];
    const float* a2s = (const float*)d_in[7];
    const float* a2d = (const float*)d_in[8];
    const float* b2 = (const float*)d_in[9];
    int N = in_sizes[0] / 128;
    int E = in_sizes[1] / 2;
    if (N > MAXN) N = MAXN;
    if (E > MAXE) E = MAXE;
    float* out = (float*)d_out;
    int nb = (N + 255) / 256;
    int grid_e = (E + 255) / 256;
    int grid_warp = (N * 32 + 255) / 256;
    int grid_g = (N + 127) / 128;

    detect_kernel<<<1, 32>>>((const int*)ei);
    zdeg_kernel<<<nb, 256>>>(N);
    decode_count_kernel<<<grid_e, 256>>>(ei, E, N);
    scan1_kernel<<<nb, 256>>>(N);
    scan2_kernel<<<1, 512>>>(nb);
    scan3_kernel<<<nb, 256>>>(N, E);
    scatter_kernel<<<grid_e, 256>>>(E);

    convert_kernel<<<4096, 256>>>(x, W1, W2, N);
    gemm1_tc_kernel<<<grid_g, 256>>>(N);
    attn_kernel<32, 1><<<(N * 4 + 255) / 256, 256>>>(a1s, a1d, N);
    gather1_kernel<<<grid_warp, 256>>>(b1, N);

    gemm2_tc_kernel<<<grid_g, 256>>>(N);
    attn_kernel<16, 2><<<(N * 4 + 255) / 256, 256>>>(a2s, a2d, N);
    gather2_kernel<<<grid_warp, 256>>>(b2, out, N);
}

// round 11
// speedup vs baseline: 3.1414x; 1.1039x over previous
#include <cuda_runtime.h>
#include <cuda_fp16.h>
#include <cuda_bf16.h>
#include <cstdint>

#define H 4
#define MAXN 100000
#define MAXE 1000000
#define NEG 0.2f
#define EPSF 1e-16f
#define SCAN_NB ((MAXN + 255) / 256)

// ---------------- scratch (device globals; no allocation allowed) ----------------
__device__ __align__(16) __half g_h1h[MAXN * 128];          // layer1 features fp16
__device__ __align__(16) __half g_h2h[MAXN * 64];           // layer2 features fp16
__device__ __align__(16) __nv_bfloat16 g_w1thi[128 * 128];  // W1^T split [n][k]
__device__ __align__(16) __nv_bfloat16 g_w1tlo[128 * 128];
__device__ __align__(16) __nv_bfloat16 g_x2hi[MAXN * 32];   // layer1 output split
__device__ __align__(16) __nv_bfloat16 g_x2lo[MAXN * 32];
__device__ __align__(16) __nv_bfloat16 g_w2thi[64 * 32];    // W2^T split [n][k]
__device__ __align__(16) __nv_bfloat16 g_w2tlo[64 * 32];
__device__ __align__(16) float g_as1[MAXN * H];
__device__ __align__(16) float g_ad1[MAXN * H];
__device__ __align__(16) float g_as2[MAXN * H];
__device__ __align__(16) float g_ad2[MAXN * H];
__device__ int g_src[MAXE];
__device__ int g_dst[MAXE];
__device__ int g_csr_src[MAXE];
__device__ int g_deg[MAXN];
__device__ int g_rowptr[MAXN + 1];
__device__ int g_wpos[MAXN];
__device__ int g_bsum[SCAN_NB];
__device__ int g_bscan[SCAN_NB];
__device__ int g_is64;

// ---------------- prep: dtype sniff + zero deg + convert weights ----------------
__global__ void prep_kernel(const int* __restrict__ ei_raw,
                            const float* __restrict__ W1,
                            const float* __restrict__ W2, int N) {
    int gt = blockIdx.x * blockDim.x + threadIdx.x;
    if (gt == 0) {
        int all0 = 1;
        for (int i = 0; i < 32; i++)
            if (ei_raw[2 * i + 1] != 0) { all0 = 0; break; }
        g_is64 = all0;
    }
    if (gt < N) g_deg[gt] = 0;
    if (gt < 128 * 128) {
        int k = gt >> 7, n = gt & 127;
        float a = W1[k * 128 + n];
        __nv_bfloat16 hv = __float2bfloat16(a);
        g_w1thi[n * 128 + k] = hv;
        g_w1tlo[n * 128 + k] = __float2bfloat16(a - __bfloat162float(hv));
    } else if (gt < 128 * 128 + 32 * 64) {
        int t = gt - 128 * 128;
        int k = t >> 6, n = t & 63;
        float a = W2[k * 64 + n];
        __nv_bfloat16 hv = __float2bfloat16(a);
        g_w2thi[n * 32 + k] = hv;
        g_w2tlo[n * 32 + k] = __float2bfloat16(a - __bfloat162float(hv));
    }
}

// ---------------- decode + degree count fused ----------------
__global__ void decode_count_kernel(const void* __restrict__ ei, int E, int N) {
    int e = blockIdx.x * blockDim.x + threadIdx.x;
    if (e >= E) return;
    int s, d;
    if (g_is64) {
        s = (int)((const long long*)ei)[e];
        d = (int)((const long long*)ei)[E + e];
    } else {
        s = ((const int*)ei)[e];
        d = ((const int*)ei)[E + e];
    }
    s = s < 0 ? 0 : (s >= N ? N - 1 : s);
    d = d < 0 ? 0 : (d >= N ? N - 1 : d);
    g_src[e] = s;
    g_dst[e] = d;
    atomicAdd(&g_deg[d], 1);
}

// ---------------- 3-kernel exclusive scan of g_deg -> g_rowptr ----------------
__global__ void scan1_kernel(int N) {
    __shared__ int s[256];
    int t = threadIdx.x;
    int i = blockIdx.x * 256 + t;
    int v = (i < N) ? g_deg[i] : 0;
    s[t] = v;
    for (int off = 1; off < 256; off <<= 1) {
        __syncthreads();
        int tv = (t >= off) ? s[t - off] : 0;
        __syncthreads();
        s[t] += tv;
    }
    __syncthreads();
    if (i < N) g_rowptr[i] = s[t] - v;
    if (t == 255) g_bsum[blockIdx.x] = s[255];
}

__global__ void scan2_kernel(int nb) {
    __shared__ int s[512];
    int t = threadIdx.x;
    int v = (t < nb) ? g_bsum[t] : 0;
    s[t] = v;
    for (int off = 1; off < 512; off <<= 1) {
        __syncthreads();
        int tv = (t >= off) ? s[t - off] : 0;
        __syncthreads();
        s[t] += tv;
    }
    __syncthreads();
    if (t < nb) g_bscan[t] = s[t] - v;
}

__global__ void scan3_kernel(int N, int E) {
    int i = blockIdx.x * blockDim.x + threadIdx.x;
    if (i < N) {
        int r = g_rowptr[i] + g_bscan[i >> 8];
        g_rowptr[i] = r;
        g_wpos[i] = r;
    }
    if (i == 0) g_rowptr[N] = E;
}

__global__ void scatter_kernel(int E) {
    int e = blockIdx.x * blockDim.x + threadIdx.x;
    if (e >= E) return;
    int d = g_dst[e];
    int p = atomicAdd(&g_wpos[d], 1);
    g_csr_src[p] = g_src[e];
}

// ---------------- bf16 mma helper ----------------
__device__ __forceinline__ void mma_bf16(float* c, uint32_t a0, uint32_t a1,
                                         uint32_t a2, uint32_t a3,
                                         uint32_t b0, uint32_t b1) {
    asm volatile(
        "mma.sync.aligned.m16n8k16.row.col.f32.bf16.bf16.f32 "
        "{%0,%1,%2,%3}, {%4,%5,%6,%7}, {%8,%9}, {%0,%1,%2,%3};\n"
        : "+f"(c[0]), "+f"(c[1]), "+f"(c[2]), "+f"(c[3])
        : "r"(a0), "r"(a1), "r"(a2), "r"(a3), "r"(b0), "r"(b1));
}

__device__ __forceinline__ uint32_t pack_hi2(float a, float b) {
    __nv_bfloat162 p = __floats2bfloat162_rn(a, b);
    return *(uint32_t*)&p;
}

// ---------------- GEMM1 (tensor): h1h[N,128] = x[N,128] @ W1 via bf16x3; x split fused ----------------
__global__ __launch_bounds__(256) void gemm1_tc_kernel(const float* __restrict__ x, int N) {
    __shared__ uint32_t As[2][128][8];  // [part][row][kpair]
    __shared__ uint32_t Bs[2][128][8];  // [part][n][kpair]
    int tid = threadIdx.x;
    int lane = tid & 31, wid = tid >> 5;
    int gid = lane >> 2, tig = lane & 3;
    int wm = (wid >> 1) * 32, wn = (wid & 1) * 64;
    int rowbase = blockIdx.x * 128;
    float c[2][8][4];
#pragma unroll
    for (int mt = 0; mt < 2; mt++)
#pragma unroll
        for (int nt = 0; nt < 8; nt++)
#pragma unroll
            for (int r = 0; r < 4; r++) c[mt][nt][r] = 0.f;

    for (int k0 = 0; k0 < 128; k0 += 16) {
        {   // A tile: load fp32 x, split to hi/lo in regs, store both parts
            int row = tid >> 1, hf = (tid & 1) * 4;  // 8 floats per thread
            int grow = rowbase + row;
            float4 v0 = make_float4(0.f, 0.f, 0.f, 0.f), v1 = v0;
            if (grow < N) {
                const float* p = &x[grow * 128 + k0 + hf * 2];
                v0 = *(const float4*)p;
                v1 = *(const float4*)(p + 4);
            }
            float f[8] = {v0.x, v0.y, v0.z, v0.w, v1.x, v1.y, v1.z, v1.w};
            uint32_t hi[4], lo[4];
#pragma unroll
            for (int q = 0; q < 4; q++) {
                float a = f[2 * q], b = f[2 * q + 1];
                float ha = __bfloat162float(__float2bfloat16(a));
                float hb = __bfloat162float(__float2bfloat16(b));
                hi[q] = pack_hi2(a, b);
                lo[q] = pack_hi2(a - ha, b - hb);
            }
            *(uint4*)&As[0][row][hf] = make_uint4(hi[0], hi[1], hi[2], hi[3]);
            *(uint4*)&As[1][row][hf] = make_uint4(lo[0], lo[1], lo[2], lo[3]);
        }
#pragma unroll
        for (int i = 0; i < 2; i++) {  // B tile
            int cc = tid + i * 256;
            int part = cc >> 8, rem = cc & 255;
            int n = rem >> 1, hf = (rem & 1) * 4;
            const __nv_bfloat16* sp = part ? g_w1tlo : g_w1thi;
            *(uint4*)&Bs[part][n][hf] = *(const uint4*)&sp[n * 128 + k0 + hf * 2];
        }
        __syncthreads();
        uint32_t af[2][2][4];
#pragma unroll
        for (int p = 0; p < 2; p++)
#pragma unroll
            for (int mt = 0; mt < 2; mt++) {
                int r = wm + mt * 16 + gid;
                af[p][mt][0] = As[p][r][tig];
                af[p][mt][1] = As[p][r + 8][tig];
                af[p][mt][2] = As[p][r][tig + 4];
                af[p][mt][3] = As[p][r + 8][tig + 4];
            }
#pragma unroll
        for (int combo = 0; combo < 3; combo++) {
            int pa = (combo == 2) ? 1 : 0;
            int pb = (combo == 1) ? 1 : 0;
#pragma unroll
            for (int nt = 0; nt < 8; nt++) {
                int nr = wn + nt * 8 + gid;
                uint32_t b0 = Bs[pb][nr][tig];
                uint32_t b1 = Bs[pb][nr][tig + 4];
                mma_bf16(c[0][nt], af[pa][0][0], af[pa][0][1], af[pa][0][2], af[pa][0][3], b0, b1);
                mma_bf16(c[1][nt], af[pa][1][0], af[pa][1][1], af[pa][1][2], af[pa][1][3], b0, b1);
            }
        }
        __syncthreads();
    }
#pragma unroll
    for (int mt = 0; mt < 2; mt++)
#pragma unroll
        for (int nt = 0; nt < 8; nt++) {
            int row = rowbase + wm + mt * 16 + gid;
            int col = wn + nt * 8 + tig * 2;
            if (row < N)
                *(__half2*)&g_h1h[row * 128 + col] = __floats2half2_rn(c[mt][nt][0], c[mt][nt][1]);
            if (row + 8 < N)
                *(__half2*)&g_h1h[(row + 8) * 128 + col] = __floats2half2_rn(c[mt][nt][2], c[mt][nt][3]);
        }
}

// ---------------- GEMM2 (tensor): h2h[N,64] = x2[N,32] @ W2 via bf16x3 ----------------
__global__ __launch_bounds__(256) void gemm2_tc_kernel(int N) {
    __shared__ uint32_t As[2][128][16];  // K=32 -> 16 pairs
    __shared__ uint32_t Bs[2][64][16];
    int tid = threadIdx.x;
    int lane = tid & 31, wid = tid >> 5;
    int gid = lane >> 2, tig = lane & 3;
    int wm = (wid >> 1) * 32, wn = (wid & 1) * 32;
    int rowbase = blockIdx.x * 128;
    float c[2][4][4];
#pragma unroll
    for (int mt = 0; mt < 2; mt++)
#pragma unroll
        for (int nt = 0; nt < 4; nt++)
#pragma unroll
            for (int r = 0; r < 4; r++) c[mt][nt][r] = 0.f;
#pragma unroll
    for (int i = 0; i < 4; i++) {  // A tile: 1024 chunks of 16B
        int cc = tid + i * 256;
        int part = cc >> 9, rem = cc & 511;
        int row = rem >> 2, hf = (rem & 3) * 4;
        const __nv_bfloat16* sp = part ? g_x2lo : g_x2hi;
        int grow = rowbase + row;
        uint4 v = make_uint4(0u, 0u, 0u, 0u);
        if (grow < N) v = *(const uint4*)&sp[grow * 32 + hf * 2];
        *(uint4*)&As[part][row][hf] = v;
    }
#pragma unroll
    for (int i = 0; i < 2; i++) {  // B tile: 512 chunks
        int cc = tid + i * 256;
        int part = cc >> 8, rem = cc & 255;
        int n = rem >> 2, hf = (rem & 3) * 4;
        const __nv_bfloat16* sp = part ? g_w2tlo : g_w2thi;
        *(uint4*)&Bs[part][n][hf] = *(const uint4*)&sp[n * 32 + hf * 2];
    }
    __syncthreads();
#pragma unroll
    for (int kc = 0; kc < 2; kc++) {
        uint32_t af[2][2][4];
#pragma unroll
        for (int p = 0; p < 2; p++)
#pragma unroll
            for (int mt = 0; mt < 2; mt++) {
                int r = wm + mt * 16 + gid;
                af[p][mt][0] = As[p][r][tig + kc * 8];
                af[p][mt][1] = As[p][r + 8][tig + kc * 8];
                af[p][mt][2] = As[p][r][tig + 4 + kc * 8];
                af[p][mt][3] = As[p][r + 8][tig + 4 + kc * 8];
            }
#pragma unroll
        for (int combo = 0; combo < 3; combo++) {
            int pa = (combo == 2) ? 1 : 0;
            int pb = (combo == 1) ? 1 : 0;
#pragma unroll
            for (int nt = 0; nt < 4; nt++) {
                int nr = wn + nt * 8 + gid;
                uint32_t b0 = Bs[pb][nr][tig + kc * 8];
                uint32_t b1 = Bs[pb][nr][tig + 4 + kc * 8];
                mma_bf16(c[0][nt], af[pa][0][0], af[pa][0][1], af[pa][0][2], af[pa][0][3], b0, b1);
                mma_bf16(c[1][nt], af[pa][1][0], af[pa][1][1], af[pa][1][2], af[pa][1][3], b0, b1);
            }
        }
    }
#pragma unroll
    for (int mt = 0; mt < 2; mt++)
#pragma unroll
        for (int nt = 0; nt < 4; nt++) {
            int row = rowbase + wm + mt * 16 + gid;
            int col = wn + nt * 8 + tig * 2;
            if (row < N)
                *(__half2*)&g_h2h[row * 64 + col] = __floats2half2_rn(c[mt][nt][0], c[mt][nt][1]);
            if (row + 8 < N)
                *(__half2*)&g_h2h[(row + 8) * 64 + col] = __floats2half2_rn(c[mt][nt][2], c[mt][nt][3]);
        }
}

// ---------------- per-node attention halves ----------------
template <int F, int LAYER>
__global__ __launch_bounds__(256) void attn_kernel(const float* __restrict__ a_src,
                                                   const float* __restrict__ a_dst, int N) {
    int i = blockIdx.x * blockDim.x + threadIdx.x;
    if (i >= N * H) return;
    int hh = i & 3;
    const __half* h = (LAYER == 1) ? g_h1h : g_h2h;
    float* as_ = (LAYER == 1) ? g_as1 : g_as2;
    float* ad_ = (LAYER == 1) ? g_ad1 : g_ad2;
    const __half* row = h + (size_t)i * F;
    const float* av = a_src + hh * F;
    const float* bv = a_dst + hh * F;
    float s = 0.f, d = 0.f;
#pragma unroll
    for (int f = 0; f < F; f += 2) {
        float2 hv = __half22float2(*(const __half2*)&row[f]);
        s += hv.x * av[f] + hv.y * av[f + 1];
        d += hv.x * bv[f] + hv.y * bv[f + 1];
    }
    as_[i] = s;
    ad_[i] = d;
}

// ---------------- gather layer 1: warp/dst; fp16 rows; 2-edge ILP; emits x2 bf16 hi/lo ----------------
__global__ __launch_bounds__(256) void gather1_kernel(const float* __restrict__ b, int N) {
    int gt = blockIdx.x * 256 + threadIdx.x;
    int d = gt >> 5;
    if (d >= N) return;
    int lane = gt & 31;
    int head = lane >> 3;
    int beg = g_rowptr[d], end = g_rowptr[d + 1];
    float adh = g_ad1[d * 4 + head];
    float a0 = 0.f, a1 = 0.f, a2 = 0.f, a3 = 0.f, dsum = 0.f;
    int j = beg;
    for (; j + 2 <= end; j += 2) {
        int s0 = g_csr_src[j];
        int s1 = g_csr_src[j + 1];
        float sc0 = g_as1[s0 * 4 + head] + adh;
        float sc1 = g_as1[s1 * 4 + head] + adh;
        uint2 r0 = *(const uint2*)&g_h1h[s0 * 128 + lane * 4];
        uint2 r1 = *(const uint2*)&g_h1h[s1 * 128 + lane * 4];
        sc0 = sc0 > 0.f ? sc0 : NEG * sc0;
        sc1 = sc1 > 0.f ? sc1 : NEG * sc1;
        float e0 = __expf(sc0), e1 = __expf(sc1);
        float2 f00 = __half22float2(*(__half2*)&r0.x);
        float2 f01 = __half22float2(*(__half2*)&r0.y);
        float2 f10 = __half22float2(*(__half2*)&r1.x);
        float2 f11 = __half22float2(*(__half2*)&r1.y);
        a0 += e0 * f00.x + e1 * f10.x;
        a1 += e0 * f00.y + e1 * f10.y;
        a2 += e0 * f01.x + e1 * f11.x;
        a3 += e0 * f01.y + e1 * f11.y;
        dsum += e0 + e1;
    }
    if (j < end) {
        int s = g_csr_src[j];
        float sc = g_as1[s * 4 + head] + adh;
        sc = sc > 0.f ? sc : NEG * sc;
        float ex = __expf(sc);
        uint2 raw = *(const uint2*)&g_h1h[s * 128 + lane * 4];
        float2 f0 = __half22float2(*(__half2*)&raw.x);
        float2 f1 = __half22float2(*(__half2*)&raw.y);
        a0 += ex * f0.x; a1 += ex * f0.y; a2 += ex * f1.x; a3 += ex * f1.y;
        dsum += ex;
    }
    float inv = 1.f / (dsum + EPSF);
    a0 *= inv; a1 *= inv; a2 *= inv; a3 *= inv;
#pragma unroll
    for (int m = 8; m <= 16; m <<= 1) {
        a0 += __shfl_xor_sync(0xffffffffu, a0, m);
        a1 += __shfl_xor_sync(0xffffffffu, a1, m);
        a2 += __shfl_xor_sync(0xffffffffu, a2, m);
        a3 += __shfl_xor_sync(0xffffffffu, a3, m);
    }
    if (lane < 8) {
        float4 bb = *(const float4*)&b[lane * 4];
        float o0 = 0.25f * a0 + bb.x, o1 = 0.25f * a1 + bb.y;
        float o2 = 0.25f * a2 + bb.z, o3 = 0.25f * a3 + bb.w;
        o0 = o0 > 0.f ? o0 : 0.f; o1 = o1 > 0.f ? o1 : 0.f;
        o2 = o2 > 0.f ? o2 : 0.f; o3 = o3 > 0.f ? o3 : 0.f;
        float h0 = __bfloat162float(__float2bfloat16(o0));
        float h1 = __bfloat162float(__float2bfloat16(o1));
        float h2 = __bfloat162float(__float2bfloat16(o2));
        float h3 = __bfloat162float(__float2bfloat16(o3));
        int base = d * 32 + lane * 4;
        ((uint32_t*)&g_x2hi[base])[0] = pack_hi2(o0, o1);
        ((uint32_t*)&g_x2hi[base])[1] = pack_hi2(o2, o3);
        ((uint32_t*)&g_x2lo[base])[0] = pack_hi2(o0 - h0, o1 - h1);
        ((uint32_t*)&g_x2lo[base])[1] = pack_hi2(o2 - h2, o3 - h3);
    }
}

// ---------------- gather layer 2: warp/dst, 2 edges per iter; write output ----------------
__global__ __launch_bounds__(256) void gather2_kernel(const float* __restrict__ b,
                                                      float* __restrict__ out, int N) {
    int gt = blockIdx.x * 256 + threadIdx.x;
    int d = gt >> 5;
    if (d >= N) return;
    int lane = gt & 31;
    int sub = lane >> 4;      // edge parity
    int l = lane & 15;        // feats l*4..l*4+3
    int head = l >> 2;
    int beg = g_rowptr[d], end = g_rowptr[d + 1];
    float adh = g_ad2[d * 4 + head];
    float a0 = 0.f, a1 = 0.f, a2 = 0.f, a3 = 0.f, dsum = 0.f;
    for (int j = beg + sub; j < end; j += 2) {
        int s = g_csr_src[j];
        float sc = g_as2[s * 4 + head] + adh;
        sc = sc > 0.f ? sc : NEG * sc;
        float ex = __expf(sc);
        uint2 raw = *(const uint2*)&g_h2h[s * 64 + l * 4];
        float2 f0 = __half22float2(*(__half2*)&raw.x);
        float2 f1 = __half22float2(*(__half2*)&raw.y);
        a0 += ex * f0.x; a1 += ex * f0.y; a2 += ex * f1.x; a3 += ex * f1.y;
        dsum += ex;
    }
    // combine edge halves
    a0 += __shfl_xor_sync(0xffffffffu, a0, 16);
    a1 += __shfl_xor_sync(0xffffffffu, a1, 16);
    a2 += __shfl_xor_sync(0xffffffffu, a2, 16);
    a3 += __shfl_xor_sync(0xffffffffu, a3, 16);
    dsum += __shfl_xor_sync(0xffffffffu, dsum, 16);
    float inv = 1.f / (dsum + EPSF);
    a0 *= inv; a1 *= inv; a2 *= inv; a3 *= inv;
    // mean over heads (head bits 2,3 of l)
#pragma unroll
    for (int m = 4; m <= 8; m <<= 1) {
        a0 += __shfl_xor_sync(0xffffffffu, a0, m);
        a1 += __shfl_xor_sync(0xffffffffu, a1, m);
        a2 += __shfl_xor_sync(0xffffffffu, a2, m);
        a3 += __shfl_xor_sync(0xffffffffu, a3, m);
    }
    if (lane < 4) {
        float4 bb = *(const float4*)&b[lane * 4];
        float4 o;
        o.x = 0.25f * a0 + bb.x; o.y = 0.25f * a1 + bb.y;
        o.z = 0.25f * a2 + bb.z; o.w = 0.25f * a3 + bb.w;
        *(float4*)&out[d * 16 + lane * 4] = o;
    }
}

extern "C" void kernel_launch(void* const* d_in, const int* in_sizes, int n_in,
                              void* d_out, int out_size) {
    const float* x = (const float*)d_in[0];
    const void* ei = d_in[1];
    const float* W1 = (const float*)d_in[2];
    const float* a1s = (const float*)d_in[3];
    const float* a1d = (const float*)d_in[4];
    const float* b1 = (const float*)d_in[5];
    const float* W2 = (const float*)d_in[6];
    const float* a2s = (const float*)d_in[7];
    const float* a2d = (const float*)d_in[8];
    const float* b2 = (const float*)d_in[9];
    int N = in_sizes[0] / 128;
    int E = in_sizes[1] / 2;
    if (N > MAXN) N = MAXN;
    if (E > MAXE) E = MAXE;
    float* out = (float*)d_out;
    int nb = (N + 255) / 256;
    int grid_e = (E + 255) / 256;
    int grid_warp = (N * 32 + 255) / 256;
    int grid_g = (N + 127) / 128;

    prep_kernel<<<nb, 256>>>((const int*)ei, W1, W2, N);          // 1
    decode_count_kernel<<<grid_e, 256>>>(ei, E, N);               // 2
    scan1_kernel<<<nb, 256>>>(N);                                 // 3
    scan2_kernel<<<1, 512>>>(nb);                                 // 4
    scan3_kernel<<<nb, 256>>>(N, E);                              // 5
    gemm1_tc_kernel<<<grid_g, 256>>>(x, N);                       // 6  <- ncu captures this
    scatter_kernel<<<grid_e, 256>>>(E);                           // 7
    attn_kernel<32, 1><<<(N * 4 + 255) / 256, 256>>>(a1s, a1d, N);// 8
    gather1_kernel<<<grid_warp, 256>>>(b1, N);                    // 9
    gemm2_tc_kernel<<<grid_g, 256>>>(N);                          // 10
    attn_kernel<16, 2><<<(N * 4 + 255) / 256, 256>>>(a2s, a2d, N);// 11
    gather2_kernel<<<grid_warp, 256>>>(b2, out, N);               // 12
}

// round 12
// speedup vs baseline: 3.1732x; 1.0101x over previous
#include <cuda_runtime.h>
#include <cuda_fp16.h>
#include <cuda_bf16.h>
#include <cstdint>

#define H 4
#define MAXN 100000
#define MAXE 1000000
#define NEG 0.2f
#define EPSF 1e-16f
#define SCAN_NB ((MAXN + 255) / 256)

// ---------------- scratch (device globals; no allocation allowed) ----------------
__device__ __align__(16) __half g_h1h[MAXN * 128];          // layer1 features fp16
__device__ __align__(16) __half g_h2h[MAXN * 64];           // layer2 features fp16
__device__ __align__(16) __nv_bfloat16 g_w1thi[128 * 128];  // W1^T split [n][k]
__device__ __align__(16) __nv_bfloat16 g_w1tlo[128 * 128];
__device__ __align__(16) float g_as1[MAXN * H];
__device__ __align__(16) float g_ad1[MAXN * H];
__device__ __align__(16) float g_as2[MAXN * H];
__device__ __align__(16) float g_ad2[MAXN * H];
__device__ int g_src[MAXE];
__device__ int g_dst[MAXE];
__device__ int g_csr_src[MAXE];
__device__ int g_deg[MAXN];
__device__ int g_rowptr[MAXN + 1];
__device__ int g_wpos[MAXN];
__device__ int g_bsum[SCAN_NB];
__device__ int g_is64;

// ---------------- prep: dtype sniff + zero deg + convert W1 ----------------
__global__ void prep_kernel(const int* __restrict__ ei_raw,
                            const float* __restrict__ W1, int N) {
    int gt = blockIdx.x * blockDim.x + threadIdx.x;
    if (gt == 0) {
        int all0 = 1;
        for (int i = 0; i < 32; i++)
            if (ei_raw[2 * i + 1] != 0) { all0 = 0; break; }
        g_is64 = all0;
    }
    if (gt < N) g_deg[gt] = 0;
    if (gt < 128 * 128) {
        int k = gt >> 7, n = gt & 127;
        float a = W1[k * 128 + n];
        __nv_bfloat16 hv = __float2bfloat16(a);
        g_w1thi[n * 128 + k] = hv;
        g_w1tlo[n * 128 + k] = __float2bfloat16(a - __bfloat162float(hv));
    }
}

// ---------------- decode + degree count fused ----------------
__global__ void decode_count_kernel(const void* __restrict__ ei, int E, int N) {
    int e = blockIdx.x * blockDim.x + threadIdx.x;
    if (e >= E) return;
    int s, d;
    if (g_is64) {
        s = (int)((const long long*)ei)[e];
        d = (int)((const long long*)ei)[E + e];
    } else {
        s = ((const int*)ei)[e];
        d = ((const int*)ei)[E + e];
    }
    s = s < 0 ? 0 : (s >= N ? N - 1 : s);
    d = d < 0 ? 0 : (d >= N ? N - 1 : d);
    g_src[e] = s;
    g_dst[e] = d;
    atomicAdd(&g_deg[d], 1);
}

// ---------------- scan part 1: per-block exclusive scan + block sums ----------------
__global__ void scan1_kernel(int N) {
    __shared__ int s[256];
    int t = threadIdx.x;
    int i = blockIdx.x * 256 + t;
    int v = (i < N) ? g_deg[i] : 0;
    s[t] = v;
    for (int off = 1; off < 256; off <<= 1) {
        __syncthreads();
        int tv = (t >= off) ? s[t - off] : 0;
        __syncthreads();
        s[t] += tv;
    }
    __syncthreads();
    if (i < N) g_rowptr[i] = s[t] - v;
    if (t == 255) g_bsum[blockIdx.x] = s[255];
}

// ---------------- scan part 2: add prefix of block sums (computed per block) ----------------
__global__ void scan3_kernel(int N, int E, int nb) {
    __shared__ int red[256];
    int t = threadIdx.x;
    int blk = blockIdx.x;
    // prefix = sum of g_bsum[0..blk-1]
    int part = 0;
    for (int i = t; i < blk; i += 256) part += g_bsum[i];
    red[t] = part;
    __syncthreads();
    for (int off = 128; off > 0; off >>= 1) {
        if (t < off) red[t] += red[t + off];
        __syncthreads();
    }
    int offv = red[0];
    int i = blk * 256 + t;
    if (i < N) {
        int r = g_rowptr[i] + offv;
        g_rowptr[i] = r;
        g_wpos[i] = r;
    }
    if (i == 0) g_rowptr[N] = E;
}

__global__ void scatter_kernel(int E) {
    int e = blockIdx.x * blockDim.x + threadIdx.x;
    if (e >= E) return;
    int d = g_dst[e];
    int p = atomicAdd(&g_wpos[d], 1);
    g_csr_src[p] = g_src[e];
}

// ---------------- bf16 mma helper ----------------
__device__ __forceinline__ void mma_bf16(float* c, uint32_t a0, uint32_t a1,
                                         uint32_t a2, uint32_t a3,
                                         uint32_t b0, uint32_t b1) {
    asm volatile(
        "mma.sync.aligned.m16n8k16.row.col.f32.bf16.bf16.f32 "
        "{%0,%1,%2,%3}, {%4,%5,%6,%7}, {%8,%9}, {%0,%1,%2,%3};\n"
        : "+f"(c[0]), "+f"(c[1]), "+f"(c[2]), "+f"(c[3])
        : "r"(a0), "r"(a1), "r"(a2), "r"(a3), "r"(b0), "r"(b1));
}

__device__ __forceinline__ uint32_t pack_hi2(float a, float b) {
    __nv_bfloat162 p = __floats2bfloat162_rn(a, b);
    return *(uint32_t*)&p;
}

// ---------------- GEMM1 (tensor): h1h[N,128] = x[N,128] @ W1 via bf16x3; x split fused ----------------
__global__ __launch_bounds__(256) void gemm1_tc_kernel(const float* __restrict__ x, int N) {
    __shared__ uint32_t As[2][128][8];  // [part][row][kpair]
    __shared__ uint32_t Bs[2][128][8];  // [part][n][kpair]
    int tid = threadIdx.x;
    int lane = tid & 31, wid = tid >> 5;
    int gid = lane >> 2, tig = lane & 3;
    int wm = (wid >> 1) * 32, wn = (wid & 1) * 64;
    int rowbase = blockIdx.x * 128;
    float c[2][8][4];
#pragma unroll
    for (int mt = 0; mt < 2; mt++)
#pragma unroll
        for (int nt = 0; nt < 8; nt++)
#pragma unroll
            for (int r = 0; r < 4; r++) c[mt][nt][r] = 0.f;

    for (int k0 = 0; k0 < 128; k0 += 16) {
        {   // A tile: load fp32 x, split to hi/lo in regs, store both parts
            int row = tid >> 1, hf = (tid & 1) * 4;  // 8 floats per thread
            int grow = rowbase + row;
            float4 v0 = make_float4(0.f, 0.f, 0.f, 0.f), v1 = v0;
            if (grow < N) {
                const float* p = &x[grow * 128 + k0 + hf * 2];
                v0 = *(const float4*)p;
                v1 = *(const float4*)(p + 4);
            }
            float f[8] = {v0.x, v0.y, v0.z, v0.w, v1.x, v1.y, v1.z, v1.w};
            uint32_t hi[4], lo[4];
#pragma unroll
            for (int q = 0; q < 4; q++) {
                float a = f[2 * q], b = f[2 * q + 1];
                float ha = __bfloat162float(__float2bfloat16(a));
                float hb = __bfloat162float(__float2bfloat16(b));
                hi[q] = pack_hi2(a, b);
                lo[q] = pack_hi2(a - ha, b - hb);
            }
            *(uint4*)&As[0][row][hf] = make_uint4(hi[0], hi[1], hi[2], hi[3]);
            *(uint4*)&As[1][row][hf] = make_uint4(lo[0], lo[1], lo[2], lo[3]);
        }
#pragma unroll
        for (int i = 0; i < 2; i++) {  // B tile
            int cc = tid + i * 256;
            int part = cc >> 8, rem = cc & 255;
            int n = rem >> 1, hf = (rem & 1) * 4;
            const __nv_bfloat16* sp = part ? g_w1tlo : g_w1thi;
            *(uint4*)&Bs[part][n][hf] = *(const uint4*)&sp[n * 128 + k0 + hf * 2];
        }
        __syncthreads();
        uint32_t af[2][2][4];
#pragma unroll
        for (int p = 0; p < 2; p++)
#pragma unroll
            for (int mt = 0; mt < 2; mt++) {
                int r = wm + mt * 16 + gid;
                af[p][mt][0] = As[p][r][tig];
                af[p][mt][1] = As[p][r + 8][tig];
                af[p][mt][2] = As[p][r][tig + 4];
                af[p][mt][3] = As[p][r + 8][tig + 4];
            }
#pragma unroll
        for (int combo = 0; combo < 3; combo++) {
            int pa = (combo == 2) ? 1 : 0;
            int pb = (combo == 1) ? 1 : 0;
#pragma unroll
            for (int nt = 0; nt < 8; nt++) {
                int nr = wn + nt * 8 + gid;
                uint32_t b0 = Bs[pb][nr][tig];
                uint32_t b1 = Bs[pb][nr][tig + 4];
                mma_bf16(c[0][nt], af[pa][0][0], af[pa][0][1], af[pa][0][2], af[pa][0][3], b0, b1);
                mma_bf16(c[1][nt], af[pa][1][0], af[pa][1][1], af[pa][1][2], af[pa][1][3], b0, b1);
            }
        }
        __syncthreads();
    }
#pragma unroll
    for (int mt = 0; mt < 2; mt++)
#pragma unroll
        for (int nt = 0; nt < 8; nt++) {
            int row = rowbase + wm + mt * 16 + gid;
            int col = wn + nt * 8 + tig * 2;
            if (row < N)
                *(__half2*)&g_h1h[row * 128 + col] = __floats2half2_rn(c[mt][nt][0], c[mt][nt][1]);
            if (row + 8 < N)
                *(__half2*)&g_h1h[(row + 8) * 128 + col] = __floats2half2_rn(c[mt][nt][2], c[mt][nt][3]);
        }
}

// ---------------- attention halves for layer 1 ----------------
__global__ __launch_bounds__(256) void attn1_kernel(const float* __restrict__ a_src,
                                                    const float* __restrict__ a_dst, int N) {
    int i = blockIdx.x * blockDim.x + threadIdx.x;
    if (i >= N * H) return;
    int hh = i & 3;
    const __half* row = g_h1h + (size_t)i * 32;
    const float* av = a_src + hh * 32;
    const float* bv = a_dst + hh * 32;
    float s = 0.f, d = 0.f;
#pragma unroll
    for (int f = 0; f < 32; f += 2) {
        float2 hv = __half22float2(*(const __half2*)&row[f]);
        s += hv.x * av[f] + hv.y * av[f + 1];
        d += hv.x * bv[f] + hv.y * bv[f + 1];
    }
    g_as1[i] = s;
    g_ad1[i] = d;
}

// ---------------- gather layer 1 FUSED: softmax-agg + mean + bias + relu + gemm2 + attn2 ----------------
__global__ __launch_bounds__(256) void gather1_fused_kernel(const float* __restrict__ b,
                                                            const float* __restrict__ W2,
                                                            const float* __restrict__ a2s,
                                                            const float* __restrict__ a2d,
                                                            int N) {
    __shared__ float2 Ws[32][32];     // W2 as float2: Ws[k][c] = (W2[k][2c], W2[k][2c+1])
    __shared__ float x2buf[8][32];    // per-warp x2 row
    int tid = threadIdx.x;
    {   // stage W2 (32x64 fp32 = 2048 floats = 1024 float2); 256 threads x 4
#pragma unroll
        for (int i = 0; i < 4; i++) {
            int idx = tid + i * 256;          // 0..1023
            int k = idx >> 5, c = idx & 31;
            Ws[k][c] = *(const float2*)&W2[k * 64 + c * 2];
        }
    }
    __syncthreads();

    int gt = blockIdx.x * 256 + tid;
    int d = gt >> 5;
    if (d >= N) return;
    int lane = gt & 31;
    int w = (tid >> 5);
    int head = lane >> 3;
    int beg = g_rowptr[d], end = g_rowptr[d + 1];
    float adh = g_ad1[d * 4 + head];
    float a0 = 0.f, a1 = 0.f, a2 = 0.f, a3 = 0.f, dsum = 0.f;
    int j = beg;
    for (; j + 2 <= end; j += 2) {
        int s0 = g_csr_src[j];
        int s1 = g_csr_src[j + 1];
        float sc0 = g_as1[s0 * 4 + head] + adh;
        float sc1 = g_as1[s1 * 4 + head] + adh;
        uint2 r0 = *(const uint2*)&g_h1h[s0 * 128 + lane * 4];
        uint2 r1 = *(const uint2*)&g_h1h[s1 * 128 + lane * 4];
        sc0 = sc0 > 0.f ? sc0 : NEG * sc0;
        sc1 = sc1 > 0.f ? sc1 : NEG * sc1;
        float e0 = __expf(sc0), e1 = __expf(sc1);
        float2 f00 = __half22float2(*(__half2*)&r0.x);
        float2 f01 = __half22float2(*(__half2*)&r0.y);
        float2 f10 = __half22float2(*(__half2*)&r1.x);
        float2 f11 = __half22float2(*(__half2*)&r1.y);
        a0 += e0 * f00.x + e1 * f10.x;
        a1 += e0 * f00.y + e1 * f10.y;
        a2 += e0 * f01.x + e1 * f11.x;
        a3 += e0 * f01.y + e1 * f11.y;
        dsum += e0 + e1;
    }
    if (j < end) {
        int s = g_csr_src[j];
        float sc = g_as1[s * 4 + head] + adh;
        sc = sc > 0.f ? sc : NEG * sc;
        float ex = __expf(sc);
        uint2 raw = *(const uint2*)&g_h1h[s * 128 + lane * 4];
        float2 f0 = __half22float2(*(__half2*)&raw.x);
        float2 f1 = __half22float2(*(__half2*)&raw.y);
        a0 += ex * f0.x; a1 += ex * f0.y; a2 += ex * f1.x; a3 += ex * f1.y;
        dsum += ex;
    }
    float inv = 1.f / (dsum + EPSF);
    a0 *= inv; a1 *= inv; a2 *= inv; a3 *= inv;
#pragma unroll
    for (int m = 8; m <= 16; m <<= 1) {
        a0 += __shfl_xor_sync(0xffffffffu, a0, m);
        a1 += __shfl_xor_sync(0xffffffffu, a1, m);
        a2 += __shfl_xor_sync(0xffffffffu, a2, m);
        a3 += __shfl_xor_sync(0xffffffffu, a3, m);
    }
    if (lane < 8) {
        float4 bb = *(const float4*)&b[lane * 4];
        float o0 = 0.25f * a0 + bb.x, o1 = 0.25f * a1 + bb.y;
        float o2 = 0.25f * a2 + bb.z, o3 = 0.25f * a3 + bb.w;
        x2buf[w][lane * 4 + 0] = o0 > 0.f ? o0 : 0.f;
        x2buf[w][lane * 4 + 1] = o1 > 0.f ? o1 : 0.f;
        x2buf[w][lane * 4 + 2] = o2 > 0.f ? o2 : 0.f;
        x2buf[w][lane * 4 + 3] = o3 > 0.f ? o3 : 0.f;
    }
    __syncwarp();
    // gemm2 row: h2[c0], h2[c1] for c0 = lane*2, c1 = lane*2+1
    float h0 = 0.f, h1 = 0.f;
#pragma unroll
    for (int k = 0; k < 32; k++) {
        float xv = x2buf[w][k];      // broadcast
        float2 wv = Ws[k][lane];
        h0 += xv * wv.x;
        h1 += xv * wv.y;
    }
    *(__half2*)&g_h2h[d * 64 + lane * 2] = __floats2half2_rn(h0, h1);
    // attn2: head2 = (lane*2)/16 = lane>>3; feature idx within head
    int c0f = (lane * 2) & 15;
    int h2d = lane >> 3;
    float ps = h0 * a2s[h2d * 16 + c0f] + h1 * a2s[h2d * 16 + c0f + 1];
    float pd = h0 * a2d[h2d * 16 + c0f] + h1 * a2d[h2d * 16 + c0f + 1];
#pragma unroll
    for (int m = 1; m <= 4; m <<= 1) {
        ps += __shfl_xor_sync(0xffffffffu, ps, m);
        pd += __shfl_xor_sync(0xffffffffu, pd, m);
    }
    if ((lane & 7) == 0) {
        g_as2[d * 4 + h2d] = ps;
        g_ad2[d * 4 + h2d] = pd;
    }
}

// ---------------- gather layer 2: warp/dst, 2 edges per iter; write output ----------------
__global__ __launch_bounds__(256) void gather2_kernel(const float* __restrict__ b,
                                                      float* __restrict__ out, int N) {
    int gt = blockIdx.x * 256 + threadIdx.x;
    int d = gt >> 5;
    if (d >= N) return;
    int lane = gt & 31;
    int sub = lane >> 4;      // edge parity
    int l = lane & 15;        // feats l*4..l*4+3
    int head = l >> 2;
    int beg = g_rowptr[d], end = g_rowptr[d + 1];
    float adh = g_ad2[d * 4 + head];
    float a0 = 0.f, a1 = 0.f, a2 = 0.f, a3 = 0.f, dsum = 0.f;
    for (int j = beg + sub; j < end; j += 2) {
        int s = g_csr_src[j];
        float sc = g_as2[s * 4 + head] + adh;
        sc = sc > 0.f ? sc : NEG * sc;
        float ex = __expf(sc);
        uint2 raw = *(const uint2*)&g_h2h[s * 64 + l * 4];
        float2 f0 = __half22float2(*(__half2*)&raw.x);
        float2 f1 = __half22float2(*(__half2*)&raw.y);
        a0 += ex * f0.x; a1 += ex * f0.y; a2 += ex * f1.x; a3 += ex * f1.y;
        dsum += ex;
    }
    // combine edge halves
    a0 += __shfl_xor_sync(0xffffffffu, a0, 16);
    a1 += __shfl_xor_sync(0xffffffffu, a1, 16);
    a2 += __shfl_xor_sync(0xffffffffu, a2, 16);
    a3 += __shfl_xor_sync(0xffffffffu, a3, 16);
    dsum += __shfl_xor_sync(0xffffffffu, dsum, 16);
    float inv = 1.f / (dsum + EPSF);
    a0 *= inv; a1 *= inv; a2 *= inv; a3 *= inv;
    // mean over heads (head bits 2,3 of l)
#pragma unroll
    for (int m = 4; m <= 8; m <<= 1) {
        a0 += __shfl_xor_sync(0xffffffffu, a0, m);
        a1 += __shfl_xor_sync(0xffffffffu, a1, m);
        a2 += __shfl_xor_sync(0xffffffffu, a2, m);
        a3 += __shfl_xor_sync(0xffffffffu, a3, m);
    }
    if (lane < 4) {
        float4 bb = *(const float4*)&b[lane * 4];
        float4 o;
        o.x = 0.25f * a0 + bb.x; o.y = 0.25f * a1 + bb.y;
        o.z = 0.25f * a2 + bb.z; o.w = 0.25f * a3 + bb.w;
        *(float4*)&out[d * 16 + lane * 4] = o;
    }
}

extern "C" void kernel_launch(void* const* d_in, const int* in_sizes, int n_in,
                              void* d_out, int out_size) {
    const float* x = (const float*)d_in[0];
    const void* ei = d_in[1];
    const float* W1 = (const float*)d_in[2];
    const float* a1s = (const float*)d_in[3];
    const float* a1d = (const float*)d_in[4];
    const float* b1 = (const float*)d_in[5];
    const float* W2 = (const float*)d_in[6];
    const float* a2s = (const float*)d_in[7];
    const float* a2d = (const float*)d_in[8];
    const float* b2 = (const float*)d_in[9];
    int N = in_sizes[0] / 128;
    int E = in_sizes[1] / 2;
    if (N > MAXN) N = MAXN;
    if (E > MAXE) E = MAXE;
    float* out = (float*)d_out;
    int nb = (N + 255) / 256;
    int grid_e = (E + 255) / 256;
    int grid_warp = (N * 32 + 255) / 256;
    int grid_g = (N + 127) / 128;

    prep_kernel<<<nb, 256>>>((const int*)ei, W1, N);                 // 1
    decode_count_kernel<<<grid_e, 256>>>(ei, E, N);                  // 2
    scan1_kernel<<<nb, 256>>>(N);                                    // 3
    scan3_kernel<<<nb, 256>>>(N, E, nb);                             // 4
    scatter_kernel<<<grid_e, 256>>>(E);                              // 5
    gemm1_tc_kernel<<<grid_g, 256>>>(x, N);                          // 6  <- ncu captures this
    attn1_kernel<<<(N * 4 + 255) / 256, 256>>>(a1s, a1d, N);         // 7
    gather1_fused_kernel<<<grid_warp, 256>>>(b1, W2, a2s, a2d, N);   // 8
    gather2_kernel<<<grid_warp, 256>>>(b2, out, N);                  // 9
}